// round 6
// baseline (speedup 1.0000x reference)
#include <cuda_runtime.h>
#include <cuda_fp16.h>

#define MFERNS 8
#define KBITS 12
#define DOUT 32
#define NIMG 64
#define CCH 8
#define HIMG 128
#define WIMG 128
#define HP 120
#define WP 120
#define HOUT 114
#define WOUT 114
#define TROWS 4096
#define Y3 3
#define BLK 384
#define VS 122          // votes tile row stride (floats)
#define HPAD 116        // h row length in halves (114 valid + 2 pad)
#define XROWS 11        // staged x rows per channel (Y3 + 8)
#define PXB (Y3 * WP)   // 360 pixels per block

// fp16 voting table: 8*4096*32 halves = 2 MB
__device__ uint2 g_table16[MFERNS * TROWS * DOUT / 4];

// fp16 horizontal-sum scratch: h[n][d][y][116] halves as uint2
__device__ uint2 g_h2[(size_t)NIMG * DOUT * HP * (HPAD / 4)];

// ---------------------------------------------------------------------------
// Kernel 0: convert table fp32 -> fp16 (4 float4 per thread for MLP)
// ---------------------------------------------------------------------------
__global__ __launch_bounds__(256)
void cvt_kernel(const float* __restrict__ table)
{
    int t = blockIdx.x * 256 + threadIdx.x;   // 65536 threads
#pragma unroll
    for (int j = 0; j < 4; j++) {
        int i = t + j * 65536;
        float4 v = __ldg((const float4*)table + i);
        __half2 h0 = __floats2half2_rn(v.x, v.y);
        __half2 h1 = __floats2half2_rn(v.z, v.w);
        uint2 r;
        r.x = *(unsigned*)&h0;
        r.y = *(unsigned*)&h1;
        g_table16[i] = r;
    }
}

// ---------------------------------------------------------------------------
// Kernel 1: 3 y-rows per block, 384 threads, 3 blocks/SM.
//  Phase A: words + conf -> packed (conf_fp16<<16 | word) in smem [m][pixel]
//  Phase B: cooperative fp16 table gather (lane = 4px x 8 d-chunks), fp32
//           accum -> smem votes tile [96][VS]
//  Phase H: horizontal 7-sum -> fp16 h[n][d][y][116]
// ---------------------------------------------------------------------------
__global__ __launch_bounds__(BLK, 3)
void votes_kernel(const float* __restrict__ x,
                  const float* __restrict__ thr,
                  const int* __restrict__ chan_idx,
                  const int* __restrict__ offsets)
{
    extern __shared__ float s_un[];     // union: x tile (11264 f) / votes tile (96*VS+16 f)
    __shared__ unsigned s_wc[MFERNS * PXB];   // packed conf|word, [m][pixel]
    __shared__ uint2    s_ot[96];             // {o1 | o2<<16, -10*thr bits}

    const int tid = threadIdx.x;
    const int y0  = blockIdx.x * Y3;
    const int n   = blockIdx.y;

    if (tid < 96) {
        int c1 = chan_idx[2 * tid + 0];
        int c2 = chan_idx[2 * tid + 1];
        int dy1 = offsets[4 * tid + 0];
        int dx1 = offsets[4 * tid + 1];
        int dy2 = offsets[4 * tid + 2];
        int dx2 = offsets[4 * tid + 3];
        unsigned o1 = c1 * (XROWS * 128) + dy1 * 128 + dx1;   // < 11264, fits 16b
        unsigned o2 = c2 * (XROWS * 128) + dy2 * 128 + dx2;
        uint2 ot;
        ot.x = o1 | (o2 << 16);
        float th10 = -10.0f * thr[tid];
        ot.y = *(unsigned*)&th10;
        s_ot[tid] = ot;
    }

    // ---- stage x tile: 8 ch x 11 rows x 32 float4 = 2816 float4 ----
    {
        const float4* xs = (const float4*)x;
        float4* st = (float4*)s_un;
        for (int i = tid; i < CCH * XROWS * 32; i += BLK) {
            int c = i / (XROWS * 32);
            int r = i - c * (XROWS * 32);
            st[i] = __ldg(xs + (size_t)(n * CCH + c) * 4096 + y0 * 32 + r);
        }
    }
    __syncthreads();

    // ---- Phase A: words + confidences, packed store ----
    {
        const int yl = tid >> 7;         // 0..2
        const int px = tid & 127;
        if (px < WP) {
            const int tb = yl * 128 + px;
#pragma unroll 1
            for (int m = 0; m < MFERNS; m++) {
                unsigned word = 0;
                float denom = 1.0f;
#pragma unroll
                for (int k = 0; k < KBITS; k++) {
                    uint2 ot = s_ot[m * KBITS + k];
                    float v1 = s_un[(ot.x & 0xFFFFu) + tb];
                    float v2 = s_un[(ot.x >> 16) + tb];
                    float z = fmaf(v1 - v2, 10.0f, __uint_as_float(ot.y));
                    if (z > 0.0f) word |= (1u << k);
                    denom *= (1.0f + __expf(-fabsf(z)));
                }
                float conf = __frcp_rn(denom);
                unsigned hb = (unsigned)__half_as_ushort(__float2half_rn(conf));
                s_wc[m * PXB + yl * WP + px] = (hb << 16) | word;
            }
        }
    }
    __syncthreads();

    // ---- Phase B: cooperative table gather -> fp32 smem votes tile ----
    const int warp = tid >> 5;           // 0..11
    const int lane = tid & 31;
    const int dq   = lane & 7;
    const int pin  = lane >> 3;

#pragma unroll 1
    for (int pass = 0; pass < 8; pass++) {
        int g = pass * 12 + warp;                 // pixel group 0..95
        if (g < PXB / 4) {
            int pglob = g * 4 + pin;
            float a0 = 0.f, a1 = 0.f, a2 = 0.f, a3 = 0.f;
#pragma unroll 1
            for (int b = 0; b < 2; b++) {
                unsigned p_[4];
                uint2 r_[4];
#pragma unroll
                for (int mm = 0; mm < 4; mm++)
                    p_[mm] = s_wc[(b * 4 + mm) * PXB + pglob];
#pragma unroll
                for (int mm = 0; mm < 4; mm++) {
                    int m = b * 4 + mm;
                    r_[mm] = __ldg(&g_table16[((size_t)(m * TROWS) + (p_[mm] & 0xFFFu)) * 8 + dq]);
                }
#pragma unroll
                for (int mm = 0; mm < 4; mm++) {
                    float cf = __half2float(__ushort_as_half((unsigned short)(p_[mm] >> 16)));
                    float2 f0 = __half22float2(*(__half2*)&r_[mm].x);
                    float2 f1 = __half22float2(*(__half2*)&r_[mm].y);
                    a0 = fmaf(cf, f0.x, a0);
                    a1 = fmaf(cf, f0.y, a1);
                    a2 = fmaf(cf, f1.x, a2);
                    a3 = fmaf(cf, f1.y, a3);
                }
            }
            int yl2 = pglob / WP;
            int px2 = pglob - yl2 * WP;
            float* vp = s_un + (yl2 * DOUT + dq * 4) * VS + px2;
            vp[0]      = a0;
            vp[VS]     = a1;
            vp[2 * VS] = a2;
            vp[3 * VS] = a3;
        }
    }
    __syncthreads();

    // ---- Phase H: horizontal 7-sum -> fp16 h ----
    if (lane < 29) {
#pragma unroll 1
        for (int r = warp; r < Y3 * DOUT; r += 12) {
            int yl2 = r >> 5;
            int d   = r & 31;
            const float* row = s_un + r * VS + 4 * lane;
            float2 q0 = *(const float2*)(row + 0);
            float2 q1 = *(const float2*)(row + 2);
            float2 q2 = *(const float2*)(row + 4);
            float2 q3 = *(const float2*)(row + 6);
            float2 q4 = *(const float2*)(row + 8);
            float s36 = q1.y + q2.x + q2.y + q3.x;
            float hx = q0.x + q0.y + q1.x + s36;
            float hy = q0.y + q1.x + s36 + q3.y;
            float hz = q1.x + s36 + q3.y + q4.x;
            float hw = s36 + q3.y + q4.x + q4.y;
            __half2 p0 = __floats2half2_rn(hx, hy);
            __half2 p1 = __floats2half2_rn(hz, hw);
            uint2 st;
            st.x = *(unsigned*)&p0;
            st.y = *(unsigned*)&p1;
            g_h2[((size_t)(n * DOUT + d) * HP + y0 + yl2) * (HPAD / 4) + lane] = st;
        }
    }
}

// ---------------------------------------------------------------------------
// Kernel 2: vertical 7-sum over fp16 h -> out[n][d][Y][X]
// ---------------------------------------------------------------------------
__global__ __launch_bounds__(256)
void pool_kernel(float* __restrict__ out)
{
    const int warp = threadIdx.x >> 5;
    const int lane = threadIdx.x & 31;
    if (lane > 28) return;

    const int gw = blockIdx.x * 8 + warp;
    const int h = gw & 1;
    const int nd = gw >> 1;
    const int y0 = h * 57;

    const uint2* ph = g_h2 + ((size_t)nd * HP + y0) * (HPAD / 4) + lane;
    float* po = out + (size_t)nd * (HOUT * WOUT) + (size_t)y0 * WOUT + 4 * lane;

    const float inv49 = 1.0f / 49.0f;
    float4 ring[7];
    float4 vs = make_float4(0.f, 0.f, 0.f, 0.f);

#pragma unroll
    for (int s = 0; s < 7; s++) {
        uint2 v = __ldg(ph + s * (HPAD / 4));
        float2 f0 = __half22float2(*(__half2*)&v.x);
        float2 f1 = __half22float2(*(__half2*)&v.y);
        float4 hh = make_float4(f0.x, f0.y, f1.x, f1.y);
        ring[s] = hh;
        vs.x += hh.x; vs.y += hh.y; vs.z += hh.z; vs.w += hh.w;
    }
    {
        *(float2*)po = make_float2(vs.x * inv49, vs.y * inv49);
        if (lane < 28)
            *(float2*)(po + 2) = make_float2(vs.z * inv49, vs.w * inv49);
    }

#pragma unroll 1
    for (int j = 1; j < 9; j++) {
#pragma unroll
        for (int s = 0; s < 7; s++) {
            int i = 7 * j + s;
            uint2 v = __ldg(ph + i * (HPAD / 4));
            float2 f0 = __half22float2(*(__half2*)&v.x);
            float2 f1 = __half22float2(*(__half2*)&v.y);
            float4 hh = make_float4(f0.x, f0.y, f1.x, f1.y);
            vs.x += hh.x - ring[s].x;
            vs.y += hh.y - ring[s].y;
            vs.z += hh.z - ring[s].z;
            vs.w += hh.w - ring[s].w;
            ring[s] = hh;
            float* op = po + (size_t)(i - 6) * WOUT;
            *(float2*)op = make_float2(vs.x * inv49, vs.y * inv49);
            if (lane < 28)
                *(float2*)(op + 2) = make_float2(vs.z * inv49, vs.w * inv49);
        }
    }
}

// ---------------------------------------------------------------------------
extern "C" void kernel_launch(void* const* d_in, const int* in_sizes, int n_in,
                              void* d_out, int out_size)
{
    const float* x        = (const float*)d_in[0];
    const float* thr      = (const float*)d_in[1];
    const float* table    = (const float*)d_in[2];
    const int*   chan_idx = (const int*)d_in[3];
    const int*   offsets  = (const int*)d_in[4];
    float* out = (float*)d_out;

    // union: max(x tile 11264 f, votes tile 96*VS+16 f) = 11728 floats
    const int dyn_smem = (Y3 * DOUT * VS + 16) * 4;
    cudaFuncSetAttribute(votes_kernel,
                         cudaFuncAttributeMaxDynamicSharedMemorySize, dyn_smem);

    cvt_kernel<<<256, 256>>>(table);

    dim3 g1(HP / Y3, NIMG);
    votes_kernel<<<g1, BLK, dyn_smem>>>(x, thr, chan_idx, offsets);

    pool_kernel<<<512, 256>>>(out);
}

// round 7
// speedup vs baseline: 1.0451x; 1.0451x over previous
#include <cuda_runtime.h>
#include <cuda_fp16.h>

#define MFERNS 8
#define KBITS 12
#define DOUT 32
#define NIMG 64
#define CCH 8
#define HIMG 128
#define WIMG 128
#define HP 120
#define WP 120
#define HOUT 114
#define WOUT 114
#define TROWS 4096
#define Y3 3
#define BLK 384
#define VS 122          // votes tile row stride (floats)
#define HPAD 116        // h row length in halves (114 valid + 2 pad)
#define XROWS 11        // staged x rows per channel (Y3 + 8)
#define PXB (Y3 * WP)   // 360 pixels per block

// fp16 voting table: 8*4096*32 halves = 2 MB
__device__ uint2 g_table16[MFERNS * TROWS * DOUT / 4];

// fp16 horizontal-sum scratch: h[n][d][y][116] halves as uint2
__device__ uint2 g_h2[(size_t)NIMG * DOUT * HP * (HPAD / 4)];

// ---------------------------------------------------------------------------
// Kernel 0: convert table fp32 -> fp16
// ---------------------------------------------------------------------------
__global__ __launch_bounds__(256)
void cvt_kernel(const float* __restrict__ table)
{
    int i = blockIdx.x * 256 + threadIdx.x;
    float4 v = __ldg((const float4*)table + i);
    __half2 h0 = __floats2half2_rn(v.x, v.y);
    __half2 h1 = __floats2half2_rn(v.z, v.w);
    uint2 r;
    r.x = *(unsigned*)&h0;
    r.y = *(unsigned*)&h1;
    g_table16[i] = r;
}

// ---------------------------------------------------------------------------
// Kernel 1: 3 y-rows per block, 384 threads, 3 blocks/SM.
//  Phase A: words + conf (paired f16x2 ex2) -> packed (conf16<<16 | word)
//  Phase B: cooperative fp16 table gather -> fp32 smem votes tile [96][VS]
//  Phase H: horizontal 7-sum -> fp16 h[n][d][y][116]
// ---------------------------------------------------------------------------
__global__ __launch_bounds__(BLK, 3)
void votes_kernel(const float* __restrict__ x,
                  const float* __restrict__ thr,
                  const int* __restrict__ chan_idx,
                  const int* __restrict__ offsets)
{
    extern __shared__ float s_un[];     // union: x tile (11264 f) / votes tile (96*VS+16 f)
    __shared__ unsigned s_wc[MFERNS * PXB];   // packed conf|word, [m][pixel]
    __shared__ uint2    s_ot[96];             // {o1 | o2<<16, -14.427*thr bits}

    const int tid = threadIdx.x;
    const int y0  = blockIdx.x * Y3;
    const int n   = blockIdx.y;

    if (tid < 96) {
        int c1 = chan_idx[2 * tid + 0];
        int c2 = chan_idx[2 * tid + 1];
        int dy1 = offsets[4 * tid + 0];
        int dx1 = offsets[4 * tid + 1];
        int dy2 = offsets[4 * tid + 2];
        int dx2 = offsets[4 * tid + 3];
        unsigned o1 = c1 * (XROWS * 128) + dy1 * 128 + dx1;   // < 11264, fits 16b
        unsigned o2 = c2 * (XROWS * 128) + dy2 * 128 + dx2;
        uint2 ot;
        ot.x = o1 | (o2 << 16);
        float th14 = -14.4269504089f * thr[tid];   // (1/TEMP)*log2(e) * (-thr)
        ot.y = *(unsigned*)&th14;
        s_ot[tid] = ot;
    }

    // ---- stage x tile: 8 ch x 11 rows x 32 float4 = 2816 float4 ----
    {
        const float4* xs = (const float4*)x;
        float4* st = (float4*)s_un;
        for (int i = tid; i < CCH * XROWS * 32; i += BLK) {
            int c = i / (XROWS * 32);
            int r = i - c * (XROWS * 32);
            st[i] = __ldg(xs + (size_t)(n * CCH + c) * 4096 + y0 * 32 + r);
        }
    }
    __syncthreads();

    // ---- Phase A: words + confidences (bits in base-2, paired f16x2 exp) ----
    {
        const int yl = tid >> 7;         // 0..2
        const int px = tid & 127;
        if (px < WP) {
            const int tb = yl * 128 + px;
#pragma unroll 1
            for (int m = 0; m < MFERNS; m++) {
                unsigned word = 0;
                float denom = 1.0f;
#pragma unroll
                for (int kp = 0; kp < KBITS / 2; kp++) {
                    uint2 otA = s_ot[m * KBITS + 2 * kp + 0];
                    uint2 otB = s_ot[m * KBITS + 2 * kp + 1];
                    float dA = s_un[(otA.x & 0xFFFFu) + tb] - s_un[(otA.x >> 16) + tb];
                    float dB = s_un[(otB.x & 0xFFFFu) + tb] - s_un[(otB.x >> 16) + tb];
                    float zA = fmaf(dA, 14.4269504089f, __uint_as_float(otA.y));
                    float zB = fmaf(dB, 14.4269504089f, __uint_as_float(otB.y));
                    if (zA > 0.0f) word |= (1u << (2 * kp));
                    if (zB > 0.0f) word |= (2u << (2 * kp));
                    float tA = fminf(zA, -zA);        // -|z| (base-2 exponent arg)
                    float tB = fminf(zB, -zB);
                    __half2 th2 = __floats2half2_rn(tA, tB);
                    unsigned e2;
                    asm("ex2.approx.f16x2 %0, %1;" : "=r"(e2) : "r"(*(unsigned*)&th2));
                    float2 ef = __half22float2(*(__half2*)&e2);
                    denom = fmaf(denom, ef.x, denom);   // *= (1 + eA)
                    denom = fmaf(denom, ef.y, denom);   // *= (1 + eB)
                }
                float conf = __frcp_rn(denom);
                unsigned hb = (unsigned)__half_as_ushort(__float2half_rn(conf));
                s_wc[m * PXB + yl * WP + px] = (hb << 16) | word;
            }
        }
    }
    __syncthreads();

    // ---- Phase B: cooperative table gather -> fp32 smem votes tile ----
    const int warp = tid >> 5;           // 0..11
    const int lane = tid & 31;
    const int dq   = lane & 7;
    const int pin  = lane >> 3;

#pragma unroll 1
    for (int pass = 0; pass < 8; pass++) {
        int g = pass * 12 + warp;                 // pixel group 0..95
        if (g < PXB / 4) {
            int pglob = g * 4 + pin;
            float a0 = 0.f, a1 = 0.f, a2 = 0.f, a3 = 0.f;
#pragma unroll 1
            for (int b = 0; b < 2; b++) {
                unsigned p_[4];
                uint2 r_[4];
#pragma unroll
                for (int mm = 0; mm < 4; mm++)
                    p_[mm] = s_wc[(b * 4 + mm) * PXB + pglob];
#pragma unroll
                for (int mm = 0; mm < 4; mm++) {
                    int m = b * 4 + mm;
                    r_[mm] = __ldg(&g_table16[((size_t)(m * TROWS) + (p_[mm] & 0xFFFu)) * 8 + dq]);
                }
#pragma unroll
                for (int mm = 0; mm < 4; mm++) {
                    float cf = __half2float(__ushort_as_half((unsigned short)(p_[mm] >> 16)));
                    float2 f0 = __half22float2(*(__half2*)&r_[mm].x);
                    float2 f1 = __half22float2(*(__half2*)&r_[mm].y);
                    a0 = fmaf(cf, f0.x, a0);
                    a1 = fmaf(cf, f0.y, a1);
                    a2 = fmaf(cf, f1.x, a2);
                    a3 = fmaf(cf, f1.y, a3);
                }
            }
            int yl2 = pglob / WP;
            int px2 = pglob - yl2 * WP;
            float* vp = s_un + (yl2 * DOUT + dq * 4) * VS + px2;
            vp[0]      = a0;
            vp[VS]     = a1;
            vp[2 * VS] = a2;
            vp[3 * VS] = a3;
        }
    }
    __syncthreads();

    // ---- Phase H: horizontal 7-sum -> fp16 h ----
    if (lane < 29) {
#pragma unroll 1
        for (int r = warp; r < Y3 * DOUT; r += 12) {
            int yl2 = r >> 5;
            int d   = r & 31;
            const float* row = s_un + r * VS + 4 * lane;
            float2 q0 = *(const float2*)(row + 0);
            float2 q1 = *(const float2*)(row + 2);
            float2 q2 = *(const float2*)(row + 4);
            float2 q3 = *(const float2*)(row + 6);
            float2 q4 = *(const float2*)(row + 8);
            float s36 = q1.y + q2.x + q2.y + q3.x;
            float hx = q0.x + q0.y + q1.x + s36;
            float hy = q0.y + q1.x + s36 + q3.y;
            float hz = q1.x + s36 + q3.y + q4.x;
            float hw = s36 + q3.y + q4.x + q4.y;
            __half2 p0 = __floats2half2_rn(hx, hy);
            __half2 p1 = __floats2half2_rn(hz, hw);
            uint2 st;
            st.x = *(unsigned*)&p0;
            st.y = *(unsigned*)&p1;
            g_h2[((size_t)(n * DOUT + d) * HP + y0 + yl2) * (HPAD / 4) + lane] = st;
        }
    }
}

// ---------------------------------------------------------------------------
// Kernel 2: vertical 7-sum over fp16 h -> out[n][d][Y][X]
// ---------------------------------------------------------------------------
__global__ __launch_bounds__(256)
void pool_kernel(float* __restrict__ out)
{
    const int warp = threadIdx.x >> 5;
    const int lane = threadIdx.x & 31;
    if (lane > 28) return;

    const int gw = blockIdx.x * 8 + warp;
    const int h = gw & 1;
    const int nd = gw >> 1;
    const int y0 = h * 57;

    const uint2* ph = g_h2 + ((size_t)nd * HP + y0) * (HPAD / 4) + lane;
    float* po = out + (size_t)nd * (HOUT * WOUT) + (size_t)y0 * WOUT + 4 * lane;

    const float inv49 = 1.0f / 49.0f;
    float4 ring[7];
    float4 vs = make_float4(0.f, 0.f, 0.f, 0.f);

#pragma unroll
    for (int s = 0; s < 7; s++) {
        uint2 v = __ldg(ph + s * (HPAD / 4));
        float2 f0 = __half22float2(*(__half2*)&v.x);
        float2 f1 = __half22float2(*(__half2*)&v.y);
        float4 hh = make_float4(f0.x, f0.y, f1.x, f1.y);
        ring[s] = hh;
        vs.x += hh.x; vs.y += hh.y; vs.z += hh.z; vs.w += hh.w;
    }
    {
        *(float2*)po = make_float2(vs.x * inv49, vs.y * inv49);
        if (lane < 28)
            *(float2*)(po + 2) = make_float2(vs.z * inv49, vs.w * inv49);
    }

#pragma unroll 1
    for (int j = 1; j < 9; j++) {
#pragma unroll
        for (int s = 0; s < 7; s++) {
            int i = 7 * j + s;
            uint2 v = __ldg(ph + i * (HPAD / 4));
            float2 f0 = __half22float2(*(__half2*)&v.x);
            float2 f1 = __half22float2(*(__half2*)&v.y);
            float4 hh = make_float4(f0.x, f0.y, f1.x, f1.y);
            vs.x += hh.x - ring[s].x;
            vs.y += hh.y - ring[s].y;
            vs.z += hh.z - ring[s].z;
            vs.w += hh.w - ring[s].w;
            ring[s] = hh;
            float* op = po + (size_t)(i - 6) * WOUT;
            *(float2*)op = make_float2(vs.x * inv49, vs.y * inv49);
            if (lane < 28)
                *(float2*)(op + 2) = make_float2(vs.z * inv49, vs.w * inv49);
        }
    }
}

// ---------------------------------------------------------------------------
extern "C" void kernel_launch(void* const* d_in, const int* in_sizes, int n_in,
                              void* d_out, int out_size)
{
    const float* x        = (const float*)d_in[0];
    const float* thr      = (const float*)d_in[1];
    const float* table    = (const float*)d_in[2];
    const int*   chan_idx = (const int*)d_in[3];
    const int*   offsets  = (const int*)d_in[4];
    float* out = (float*)d_out;

    const int dyn_smem = (Y3 * DOUT * VS + 16) * 4;
    cudaFuncSetAttribute(votes_kernel,
                         cudaFuncAttributeMaxDynamicSharedMemorySize, dyn_smem);

    cvt_kernel<<<1024, 256>>>(table);

    dim3 g1(HP / Y3, NIMG);
    votes_kernel<<<g1, BLK, dyn_smem>>>(x, thr, chan_idx, offsets);

    pool_kernel<<<512, 256>>>(out);
}